// round 2
// baseline (speedup 1.0000x reference)
#include <cuda_runtime.h>

// LinearEmbedded: out[a,b,d] = sum_c x[a,b,c] * W[r_b, c, d] + bias[r_b, d]
// A=128 (cells), B=128 (minibatch regions), C=512, D=512, R=1000.
// => 128 independent 128x512x512 SGEMMs with per-b gathered weight matrix.
// Round 1: fp32 FFMA SGEMM, BM=128 BN=128 BK=16, 256 thr, 8x8 per-thread tile,
// double-buffered shared memory. Grid = (D/128, B) = (4, 128) = 512 CTAs.

#define BM 128
#define BN 128
#define BK 16
#define TM 8
#define TN 8
#define AS_LD 132  // BM + 4 pad; 132*4B=528B is a multiple of 16 -> float4-safe

// Normalized region indices (handles int64-vs-int32 ambiguity of region_ix).
__device__ int g_ridx[128];

// region_ix may arrive as int32 or int64 depending on jax x64 config.
// If int64 (little-endian, values in [0,1000)), the high 32-bit word of every
// element is 0. We check the first 64 elements' high words (stays within the
// 512-byte footprint an int32 buffer would have, so no OOB either way).
__global__ void decode_idx_kernel(const unsigned int* __restrict__ p, int n) {
    __shared__ int not_i64;
    if (threadIdx.x == 0) not_i64 = 0;
    __syncthreads();
    if (threadIdx.x < 64) {
        if (p[2 * threadIdx.x + 1] != 0u) not_i64 = 1;
    }
    __syncthreads();
    int b = (int)threadIdx.x;
    if (b < n) {
        g_ridx[b] = not_i64 ? (int)p[b] : (int)p[2 * b];
    }
}

__global__ __launch_bounds__(256, 2)
void linemb_sgemm(const float* __restrict__ x,
                  const float* __restrict__ w,
                  const float* __restrict__ bias,
                  float* __restrict__ out) {
    const int B = 128, C = 512, D = 512;

    const int b  = blockIdx.y;
    const int n0 = blockIdx.x * BN;
    const int r  = g_ridx[b];

    // x[a,b,c] at (a*B + b)*C + c  -> xb[a*B*C + c]
    const float* __restrict__ xb = x + (size_t)b * C;
    const float* __restrict__ wr = w + (size_t)r * C * D;
    const float* __restrict__ br = bias + (size_t)r * D;
    float* __restrict__ ob = out + (size_t)b * D;   // ob[a*B*D + d]

    __shared__ __align__(16) float As[2][BK][AS_LD]; // As[kk][a] (transposed)
    __shared__ __align__(16) float Bs[2][BK][BN];    // Bs[kk][d]

    const int tid = (int)threadIdx.x;
    const int tx = tid & 15;   // 0..15 -> n micro-tile
    const int ty = tid >> 4;   // 0..15 -> m micro-tile

    // A-tile loader: 512 float4 chunks (128 rows x 4 quads), 2 per thread.
    const int a_row0 = tid >> 2;       // 0..63  (second load: +64)
    const int a_kq   = tid & 3;        // which 4-float quad of the 16-wide k slab
    // B-tile loader: 512 float4 chunks (16 rows x 32 quads), 2 per thread.
    const int b_kk0 = tid >> 5;        // 0..7   (second load: +8)
    const int b_dq  = tid & 31;        // 0..31

    const size_t xa_stride = (size_t)B * C;   // 65536 floats between a-rows

    float4 pa0, pa1, pb0, pb1;

    // ---- prologue: load k-tile 0 into stage 0 ----
    pa0 = *(const float4*)(xb + (size_t)a_row0        * xa_stride + a_kq * 4);
    pa1 = *(const float4*)(xb + (size_t)(a_row0 + 64) * xa_stride + a_kq * 4);
    pb0 = *(const float4*)(wr + (size_t)b_kk0       * D + n0 + b_dq * 4);
    pb1 = *(const float4*)(wr + (size_t)(b_kk0 + 8) * D + n0 + b_dq * 4);

    As[0][a_kq * 4 + 0][a_row0] = pa0.x;
    As[0][a_kq * 4 + 1][a_row0] = pa0.y;
    As[0][a_kq * 4 + 2][a_row0] = pa0.z;
    As[0][a_kq * 4 + 3][a_row0] = pa0.w;
    As[0][a_kq * 4 + 0][a_row0 + 64] = pa1.x;
    As[0][a_kq * 4 + 1][a_row0 + 64] = pa1.y;
    As[0][a_kq * 4 + 2][a_row0 + 64] = pa1.z;
    As[0][a_kq * 4 + 3][a_row0 + 64] = pa1.w;
    *(float4*)&Bs[0][b_kk0    ][b_dq * 4] = pb0;
    *(float4*)&Bs[0][b_kk0 + 8][b_dq * 4] = pb1;
    __syncthreads();

    float acc[TM][TN];
    #pragma unroll
    for (int i = 0; i < TM; ++i)
        #pragma unroll
        for (int j = 0; j < TN; ++j)
            acc[i][j] = 0.0f;

    const int NK = C / BK;  // 32

    for (int kt = 0; kt < NK; ++kt) {
        const int cur = kt & 1;

        // prefetch next k-tile from global into registers
        if (kt + 1 < NK) {
            const int ko = (kt + 1) * BK;
            pa0 = *(const float4*)(xb + (size_t)a_row0        * xa_stride + ko + a_kq * 4);
            pa1 = *(const float4*)(xb + (size_t)(a_row0 + 64) * xa_stride + ko + a_kq * 4);
            pb0 = *(const float4*)(wr + (size_t)(ko + b_kk0    ) * D + n0 + b_dq * 4);
            pb1 = *(const float4*)(wr + (size_t)(ko + b_kk0 + 8) * D + n0 + b_dq * 4);
        }

        // compute on current stage
        #pragma unroll
        for (int kk = 0; kk < BK; ++kk) {
            float af[TM], bf[TN];
            *(float4*)&af[0] = *(const float4*)&As[cur][kk][ty * 8];
            *(float4*)&af[4] = *(const float4*)&As[cur][kk][ty * 8 + 4];
            *(float4*)&bf[0] = *(const float4*)&Bs[cur][kk][tx * 8];
            *(float4*)&bf[4] = *(const float4*)&Bs[cur][kk][tx * 8 + 4];
            #pragma unroll
            for (int i = 0; i < TM; ++i)
                #pragma unroll
                for (int j = 0; j < TN; ++j)
                    acc[i][j] = fmaf(af[i], bf[j], acc[i][j]);
        }

        // store prefetched tile into the other stage
        if (kt + 1 < NK) {
            const int nxt = cur ^ 1;
            As[nxt][a_kq * 4 + 0][a_row0] = pa0.x;
            As[nxt][a_kq * 4 + 1][a_row0] = pa0.y;
            As[nxt][a_kq * 4 + 2][a_row0] = pa0.z;
            As[nxt][a_kq * 4 + 3][a_row0] = pa0.w;
            As[nxt][a_kq * 4 + 0][a_row0 + 64] = pa1.x;
            As[nxt][a_kq * 4 + 1][a_row0 + 64] = pa1.y;
            As[nxt][a_kq * 4 + 2][a_row0 + 64] = pa1.z;
            As[nxt][a_kq * 4 + 3][a_row0 + 64] = pa1.w;
            *(float4*)&Bs[nxt][b_kk0    ][b_dq * 4] = pb0;
            *(float4*)&Bs[nxt][b_kk0 + 8][b_dq * 4] = pb1;
        }
        __syncthreads();
    }

    // ---- epilogue: add bias, store ----
    float bfr[TN];
    *(float4*)&bfr[0] = *(const float4*)(br + n0 + tx * 8);
    *(float4*)&bfr[4] = *(const float4*)(br + n0 + tx * 8 + 4);

    const size_t oa_stride = (size_t)B * D;  // 65536 floats between a-rows
    #pragma unroll
    for (int i = 0; i < TM; ++i) {
        const int a = ty * 8 + i;
        float4 o0, o1;
        o0.x = acc[i][0] + bfr[0];
        o0.y = acc[i][1] + bfr[1];
        o0.z = acc[i][2] + bfr[2];
        o0.w = acc[i][3] + bfr[3];
        o1.x = acc[i][4] + bfr[4];
        o1.y = acc[i][5] + bfr[5];
        o1.z = acc[i][6] + bfr[6];
        o1.w = acc[i][7] + bfr[7];
        *(float4*)(ob + (size_t)a * oa_stride + n0 + tx * 8)     = o0;
        *(float4*)(ob + (size_t)a * oa_stride + n0 + tx * 8 + 4) = o1;
    }
}

extern "C" void kernel_launch(void* const* d_in, const int* in_sizes, int n_in,
                              void* d_out, int out_size) {
    const float*        x    = (const float*)d_in[0];
    const unsigned int* ridx = (const unsigned int*)d_in[1];
    const float*        w    = (const float*)d_in[2];
    const float*        bias = (const float*)d_in[3];
    float*              out  = (float*)d_out;

    const int Bn = in_sizes[1] > 128 ? 128 : in_sizes[1];  // 128 regions
    decode_idx_kernel<<<1, 128>>>(ridx, Bn);

    dim3 grid(512 / BN, 128);  // (D tiles, B)
    linemb_sgemm<<<grid, 256>>>(x, w, bias, out);
}

// round 4
// speedup vs baseline: 1.1827x; 1.1827x over previous
#include <cuda_runtime.h>
#include <cuda_bf16.h>
#include <cstdint>

// LinearEmbedded via mma.sync bf16 3-way split (tcgen05 unavailable: harness
// targets plain sm_103, no arch-accel features).
// out[a,b,d] = sum_c x[a,b,c]*W[r_b,c,d] + bias[r_b,d]; A=B=128, C=D=512.
// Per CTA (grid 4 x 128): M=a(128) x N=d(128), K=c(512).
// SMEM tiles stored in ldmatrix lane order: each 16x16 bf16 tile = 32
// contiguous 16B chunks, chunk index == lane index -> conflict-free LDSM.

__device__ int g_ridx[128];

__global__ void decode_idx_kernel(const unsigned int* __restrict__ p, int n) {
    __shared__ int not_i64;
    if (threadIdx.x == 0) not_i64 = 0;
    __syncthreads();
    if (threadIdx.x < 64) {
        if (p[2 * threadIdx.x + 1] != 0u) not_i64 = 1;
    }
    __syncthreads();
    int b = (int)threadIdx.x;
    if (b < n) g_ridx[b] = not_i64 ? (int)p[b] : (int)p[2 * b];
}

__device__ __forceinline__ uint32_t smem_u32(const void* p) {
    uint32_t a;
    asm("{ .reg .u64 t; cvta.to.shared.u64 t, %1; cvt.u32.u64 %0, t; }" : "=r"(a) : "l"(p));
    return a;
}

__device__ __forceinline__ void split2(float v0, float v1, uint32_t& hi, uint32_t& lo) {
    __nv_bfloat16 h0 = __float2bfloat16_rn(v0);
    __nv_bfloat16 h1 = __float2bfloat16_rn(v1);
    __nv_bfloat16 l0 = __float2bfloat16_rn(v0 - __bfloat162float(h0));
    __nv_bfloat16 l1 = __float2bfloat16_rn(v1 - __bfloat162float(h1));
    __nv_bfloat162 hp; hp.x = h0; hp.y = h1;
    __nv_bfloat162 lp; lp.x = l0; lp.y = l1;
    hi = *(uint32_t*)&hp;
    lo = *(uint32_t*)&lp;
}

__device__ __forceinline__ void ldsm4(uint32_t* r, uint32_t addr) {
    asm volatile("ldmatrix.sync.aligned.m8n8.x4.shared.b16 {%0,%1,%2,%3}, [%4];"
        : "=r"(r[0]), "=r"(r[1]), "=r"(r[2]), "=r"(r[3]) : "r"(addr));
}

__device__ __forceinline__ void mma16816(float* d, const uint32_t* a, uint32_t b0, uint32_t b1) {
    asm volatile("mma.sync.aligned.m16n8k16.row.col.f32.bf16.bf16.f32 "
        "{%0,%1,%2,%3}, {%4,%5,%6,%7}, {%8,%9}, {%0,%1,%2,%3};"
        : "+f"(d[0]), "+f"(d[1]), "+f"(d[2]), "+f"(d[3])
        : "r"(a[0]), "r"(a[1]), "r"(a[2]), "r"(a[3]), "r"(b0), "r"(b1));
}

// SMEM layout per stage (32 KB): AHI 8K | ALO 8K | BHI 8K | BLO 8K
// Each region: [k16:2][tile16:8] tiles of 512B (32 chunks x 16B).
#define STAGE_BYTES 32768
#define AHI_OFF 0
#define ALO_OFF 8192
#define BHI_OFF 16384
#define BLO_OFF 24576
#define SMEM_TOTAL (2 * STAGE_BYTES)

__global__ __launch_bounds__(256, 1)
void linemb_mma(const float* __restrict__ x,
                const float* __restrict__ w,
                const float* __restrict__ bias,
                float* __restrict__ out) {
    extern __shared__ char smem[];
    const uint32_t sb = smem_u32(smem);

    const int tid  = (int)threadIdx.x;
    const int wid  = tid >> 5;
    const int lane = tid & 31;
    const int b    = (int)blockIdx.y;
    const int d0   = (int)blockIdx.x * 128;
    const int r    = g_ridx[b];

    const float* __restrict__ xb = x + (size_t)b * 512;          // + a*65536 + c
    const float* __restrict__ wr = w + (size_t)r * 512 * 512;    // + c*512 + d
    const float* __restrict__ br = bias + (size_t)r * 512;

    // loader mapping
    const int ld_d  = tid & 127;        // W loader: d row; x loader: a row
    const int ld_o0 = (tid >> 7) * 2;   // first k-octet (of 4 in a 32-k chunk)

    // precomputed smem chunk offsets (within a stage) for this thread's 2 octets
    uint32_t boff[2], aoff[2];
    {
        const int n = ld_d & 15, t16 = ld_d >> 4;
        #pragma unroll
        for (int j = 0; j < 2; ++j) {
            const int o = ld_o0 + j, k16 = o >> 1, oct = o & 1;
            const uint32_t bidx = (uint32_t)((n & 7) + 8 * (oct + 2 * (n >> 3)));
            const uint32_t aidx = (uint32_t)((n & 7) + 8 * ((n >> 3) & 1) + 16 * oct);
            boff[j] = (uint32_t)((k16 * 8 + t16) * 512) + bidx * 16;
            aoff[j] = (uint32_t)((k16 * 8 + t16) * 512) + aidx * 16;
        }
    }

    float wv[16], xv[16];

    // ---- prefetch chunk 0 ----
    {
        const int k0 = 0;
        #pragma unroll
        for (int j = 0; j < 2; ++j) {
            const int o = ld_o0 + j;
            #pragma unroll
            for (int i = 0; i < 8; ++i)
                wv[j * 8 + i] = __ldg(wr + (size_t)(k0 + o * 8 + i) * 512 + d0 + ld_d);
            const float4 p0 = *(const float4*)(xb + (size_t)ld_d * 65536 + k0 + o * 8);
            const float4 p1 = *(const float4*)(xb + (size_t)ld_d * 65536 + k0 + o * 8 + 4);
            xv[j * 8 + 0] = p0.x; xv[j * 8 + 1] = p0.y; xv[j * 8 + 2] = p0.z; xv[j * 8 + 3] = p0.w;
            xv[j * 8 + 4] = p1.x; xv[j * 8 + 5] = p1.y; xv[j * 8 + 6] = p1.z; xv[j * 8 + 7] = p1.w;
        }
    }

    float acc[4][4][4];
    #pragma unroll
    for (int mt = 0; mt < 4; ++mt)
        #pragma unroll
        for (int nb = 0; nb < 4; ++nb)
            #pragma unroll
            for (int q = 0; q < 4; ++q)
                acc[mt][nb][q] = 0.0f;

    const int wm = wid & 1;   // 2 m-groups of 64
    const int wn = wid >> 1;  // 4 n-groups of 32

    for (int ch = 0; ch < 16; ++ch) {        // 16 chunks of K=32
        const uint32_t st = sb + (uint32_t)((ch & 1) * STAGE_BYTES);

        // ---- convert + store this chunk's regs into stage ----
        #pragma unroll
        for (int j = 0; j < 2; ++j) {
            uint32_t h[4], l[4];
            #pragma unroll
            for (int p = 0; p < 4; ++p)
                split2(wv[j * 8 + 2 * p], wv[j * 8 + 2 * p + 1], h[p], l[p]);
            asm volatile("st.shared.v4.b32 [%0], {%1,%2,%3,%4};" :: "r"(st + BHI_OFF + boff[j]), "r"(h[0]), "r"(h[1]), "r"(h[2]), "r"(h[3]) : "memory");
            asm volatile("st.shared.v4.b32 [%0], {%1,%2,%3,%4};" :: "r"(st + BLO_OFF + boff[j]), "r"(l[0]), "r"(l[1]), "r"(l[2]), "r"(l[3]) : "memory");
            #pragma unroll
            for (int p = 0; p < 4; ++p)
                split2(xv[j * 8 + 2 * p], xv[j * 8 + 2 * p + 1], h[p], l[p]);
            asm volatile("st.shared.v4.b32 [%0], {%1,%2,%3,%4};" :: "r"(st + AHI_OFF + aoff[j]), "r"(h[0]), "r"(h[1]), "r"(h[2]), "r"(h[3]) : "memory");
            asm volatile("st.shared.v4.b32 [%0], {%1,%2,%3,%4};" :: "r"(st + ALO_OFF + aoff[j]), "r"(l[0]), "r"(l[1]), "r"(l[2]), "r"(l[3]) : "memory");
        }

        // ---- prefetch next chunk ----
        if (ch + 1 < 16) {
            const int k0 = (ch + 1) * 32;
            #pragma unroll
            for (int j = 0; j < 2; ++j) {
                const int o = ld_o0 + j;
                #pragma unroll
                for (int i = 0; i < 8; ++i)
                    wv[j * 8 + i] = __ldg(wr + (size_t)(k0 + o * 8 + i) * 512 + d0 + ld_d);
                const float4 p0 = *(const float4*)(xb + (size_t)ld_d * 65536 + k0 + o * 8);
                const float4 p1 = *(const float4*)(xb + (size_t)ld_d * 65536 + k0 + o * 8 + 4);
                xv[j * 8 + 0] = p0.x; xv[j * 8 + 1] = p0.y; xv[j * 8 + 2] = p0.z; xv[j * 8 + 3] = p0.w;
                xv[j * 8 + 4] = p1.x; xv[j * 8 + 5] = p1.y; xv[j * 8 + 6] = p1.z; xv[j * 8 + 7] = p1.w;
            }
        }

        __syncthreads();

        // ---- compute: 2 k16-steps ----
        #pragma unroll
        for (int k16 = 0; k16 < 2; ++k16) {
            uint32_t ah[4][4], al[4][4], bh[2][4], bl[2][4];
            const uint32_t lof = (uint32_t)lane * 16;
            #pragma unroll
            for (int mt = 0; mt < 4; ++mt) {
                const uint32_t toff = (uint32_t)((k16 * 8 + wm * 4 + mt) * 512) + lof;
                ldsm4(ah[mt], st + AHI_OFF + toff);
                ldsm4(al[mt], st + ALO_OFF + toff);
            }
            #pragma unroll
            for (int nt = 0; nt < 2; ++nt) {
                const uint32_t toff = (uint32_t)((k16 * 8 + wn * 2 + nt) * 512) + lof;
                ldsm4(bh[nt], st + BHI_OFF + toff);
                ldsm4(bl[nt], st + BLO_OFF + toff);
            }
            #pragma unroll
            for (int mt = 0; mt < 4; ++mt) {
                #pragma unroll
                for (int nb = 0; nb < 4; ++nb) {
                    const int nt = nb >> 1, hh = (nb & 1) * 2;
                    mma16816(acc[mt][nb], ah[mt], bh[nt][hh], bh[nt][hh + 1]);
                    mma16816(acc[mt][nb], ah[mt], bl[nt][hh], bl[nt][hh + 1]);
                    mma16816(acc[mt][nb], al[mt], bh[nt][hh], bh[nt][hh + 1]);
                }
            }
        }
        __syncthreads();
    }

    // ---- epilogue: add bias, store out[a][b][d] ----
    const int tq = lane & 3;    // thread-in-group -> d pair
    const int tg = lane >> 2;   // group -> row within 8
    #pragma unroll
    for (int nb = 0; nb < 4; ++nb) {
        const int d = d0 + wn * 32 + nb * 8 + 2 * tq;
        const float2 bv = *(const float2*)(br + d);
        #pragma unroll
        for (int mt = 0; mt < 4; ++mt) {
            const int a0r = (wm * 4 + mt) * 16 + tg;
            float2 o0, o1;
            o0.x = acc[mt][nb][0] + bv.x;
            o0.y = acc[mt][nb][1] + bv.y;
            o1.x = acc[mt][nb][2] + bv.x;
            o1.y = acc[mt][nb][3] + bv.y;
            *(float2*)(out + ((size_t)a0r * 128 + b) * 512 + d)       = o0;
            *(float2*)(out + ((size_t)(a0r + 8) * 128 + b) * 512 + d) = o1;
        }
    }
}

extern "C" void kernel_launch(void* const* d_in, const int* in_sizes, int n_in,
                              void* d_out, int out_size) {
    const float*        x    = (const float*)d_in[0];
    const unsigned int* ridx = (const unsigned int*)d_in[1];
    const float*        w    = (const float*)d_in[2];
    const float*        bias = (const float*)d_in[3];
    float*              out  = (float*)d_out;

    const int Bn = in_sizes[1] > 128 ? 128 : in_sizes[1];
    decode_idx_kernel<<<1, 128>>>(ridx, Bn);

    static int smem_set = 0;
    if (!smem_set) {
        cudaFuncSetAttribute(linemb_mma, cudaFuncAttributeMaxDynamicSharedMemorySize, SMEM_TOTAL);
        smem_set = 1;
    }
    dim3 grid(4, 128);   // (d-tiles, b)
    linemb_mma<<<grid, 256, SMEM_TOTAL>>>(x, w, bias, out);
}